// round 5
// baseline (speedup 1.0000x reference)
#include <cuda_runtime.h>
#include <cuda_bf16.h>
#include <math.h>
#include <stdint.h>

#define BB 4
#define SS 2048
#define HH 2048
#define NHH 8
#define DD 256
#define QKVW 2560            // (8 + 2*1) * 256
#define MROWS (BB * SS)      // 8192

// ---------------------------------------------------------------------------
// Scratch (allocation-free rule: device globals)
// ---------------------------------------------------------------------------
__device__ float g_qkv[MROWS * QKVW];                         // ~84 MB fp32
__device__ __align__(16) __nv_bfloat16 g_hid_hi[MROWS * HH];
__device__ __align__(16) __nv_bfloat16 g_hid_lo[MROWS * HH];
__device__ __align__(16) __nv_bfloat16 g_wqkv_hi[QKVW * HH];  // transposed [N][K]
__device__ __align__(16) __nv_bfloat16 g_wqkv_lo[QKVW * HH];
__device__ __align__(16) __nv_bfloat16 g_wo_hi[HH * HH];      // transposed [N][K]
__device__ __align__(16) __nv_bfloat16 g_wo_lo[HH * HH];
__device__ __align__(16) __nv_bfloat16 g_atn_hi[MROWS * HH];
__device__ __align__(16) __nv_bfloat16 g_atn_lo[MROWS * HH];
__device__ __align__(16) __nv_bfloat16 g_q_hi[(size_t)BB * NHH * SS * DD];
__device__ __align__(16) __nv_bfloat16 g_q_lo[(size_t)BB * NHH * SS * DD];
__device__ __align__(16) __nv_bfloat16 g_k_hi[(size_t)BB * SS * DD];
__device__ __align__(16) __nv_bfloat16 g_k_lo[(size_t)BB * SS * DD];
__device__ __align__(16) __nv_bfloat16 g_v_hi[(size_t)BB * SS * DD];
__device__ __align__(16) __nv_bfloat16 g_v_lo[(size_t)BB * SS * DD];

// ---------------------------------------------------------------------------
// helpers
// ---------------------------------------------------------------------------
__device__ __forceinline__ uint32_t smem_u32(const void* p) {
    uint32_t a;
    asm("{ .reg .u64 t; cvta.to.shared.u64 t, %1; cvt.u32.u64 %0, t; }"
        : "=r"(a) : "l"(p));
    return a;
}

__device__ __forceinline__ void ldsm_x4(uint32_t (&r)[4], uint32_t addr) {
    asm volatile("ldmatrix.sync.aligned.m8n8.x4.shared.b16 {%0,%1,%2,%3}, [%4];"
                 : "=r"(r[0]), "=r"(r[1]), "=r"(r[2]), "=r"(r[3]) : "r"(addr));
}

__device__ __forceinline__ void ldsm_x4_t(uint32_t (&r)[4], uint32_t addr) {
    asm volatile("ldmatrix.sync.aligned.m8n8.x4.trans.shared.b16 {%0,%1,%2,%3}, [%4];"
                 : "=r"(r[0]), "=r"(r[1]), "=r"(r[2]), "=r"(r[3]) : "r"(addr));
}

__device__ __forceinline__ void mma_bf16(float (&d)[4], const uint32_t (&a)[4],
                                         const uint32_t* b) {
    asm volatile(
        "mma.sync.aligned.m16n8k16.row.col.f32.bf16.bf16.f32 "
        "{%0,%1,%2,%3}, {%4,%5,%6,%7}, {%8,%9}, {%0,%1,%2,%3};"
        : "+f"(d[0]), "+f"(d[1]), "+f"(d[2]), "+f"(d[3])
        : "r"(a[0]), "r"(a[1]), "r"(a[2]), "r"(a[3]), "r"(b[0]), "r"(b[1]));
}

__device__ __forceinline__ void cp16(uint32_t dst, const void* src) {
    asm volatile("cp.async.cg.shared.global [%0], [%1], 16;"
                 :: "r"(dst), "l"(src) : "memory");
}

__device__ __forceinline__ uint32_t pk_bf2(float a, float b) {
    __nv_bfloat162 t = __floats2bfloat162_rn(a, b);
    return *reinterpret_cast<uint32_t*>(&t);
}

// ---------------------------------------------------------------------------
// HMMA split-bf16 GEMM (unchanged, verified)
// ---------------------------------------------------------------------------
#define ROWB 80
#define TILEB (128 * ROWB)
#define STAGEB (4 * TILEB)
#define GEMM_SMEM (2 * STAGEB)

__global__ __launch_bounds__(256) void hmma_gemm_kernel(
    const __nv_bfloat16* __restrict__ Ahi, const __nv_bfloat16* __restrict__ Alo,
    const __nv_bfloat16* __restrict__ Bhi, const __nv_bfloat16* __restrict__ Blo,
    float* __restrict__ C, int M, int N, int K)
{
    extern __shared__ char gsm[];
    const uint32_t base = smem_u32(gsm);

    const int tid = threadIdx.x;
    const int lane = tid & 31;
    const int wid = tid >> 5;
    const int warp_m = wid & 1;
    const int warp_n = wid >> 1;
    const int row0 = blockIdx.y * 128, col0 = blockIdx.x * 128;

    float acc[4][4][4];
#pragma unroll
    for (int i = 0; i < 4; i++)
#pragma unroll
        for (int j = 0; j < 4; j++)
#pragma unroll
            for (int e = 0; e < 4; e++) acc[i][j][e] = 0.f;

    const int nch = K >> 5;

    auto load_stage = [&](int st, int k0) {
        const uint32_t sb = base + st * STAGEB;
#pragma unroll
        for (int i2 = 0; i2 < 8; i2++) {
            int g = tid + (i2 << 8);
            int t = g >> 9;
            int rem = g & 511;
            int r = rem >> 2, kq = rem & 3;
            const __nv_bfloat16* bp = (t == 0) ? Ahi : (t == 1) ? Alo
                                    : (t == 2) ? Bhi : Blo;
            int gr = ((t < 2) ? row0 : col0) + r;
            const __nv_bfloat16* src = bp + (size_t)gr * K + k0 + (kq << 3);
            uint32_t dst = sb + t * TILEB + r * ROWB + (kq << 4);
            cp16(dst, src);
        }
        asm volatile("cp.async.commit_group;" ::: "memory");
    };

    load_stage(0, 0);

    for (int c = 0; c < nch; c++) {
        if (c + 1 < nch) {
            load_stage((c + 1) & 1, (c + 1) << 5);
            asm volatile("cp.async.wait_group 1;" ::: "memory");
        } else {
            asm volatile("cp.async.wait_group 0;" ::: "memory");
        }
        __syncthreads();

        const uint32_t sb = base + (c & 1) * STAGEB;
        const uint32_t aH = sb, bH = sb + 2 * TILEB;

#pragma unroll
        for (int ks = 0; ks < 2; ks++) {
            uint32_t ah[4][4], al[4][4], bh[4][2], bl[4][2];
            const int arow = warp_m * 64 + (lane & 15);
            const uint32_t akoff = (ks << 5) + ((lane >> 4) << 4);
#pragma unroll
            for (int i = 0; i < 4; i++) {
                uint32_t ad = aH + (uint32_t)(arow + i * 16) * ROWB + akoff;
                ldsm_x4(ah[i], ad);
                ldsm_x4(al[i], ad + TILEB);
            }
            const int quad = lane >> 3, wi = lane & 7;
#pragma unroll
            for (int t = 0; t < 2; t++) {
                int ntile = 2 * t + (quad >> 1);
                int brow = warp_n * 32 + ntile * 8 + wi;
                uint32_t bd = bH + (uint32_t)brow * ROWB + (ks << 5) + ((quad & 1) << 4);
                uint32_t r4[4];
                ldsm_x4(r4, bd);
                bh[2 * t][0] = r4[0]; bh[2 * t][1] = r4[1];
                bh[2 * t + 1][0] = r4[2]; bh[2 * t + 1][1] = r4[3];
                ldsm_x4(r4, bd + TILEB);
                bl[2 * t][0] = r4[0]; bl[2 * t][1] = r4[1];
                bl[2 * t + 1][0] = r4[2]; bl[2 * t + 1][1] = r4[3];
            }
#pragma unroll
            for (int i = 0; i < 4; i++)
#pragma unroll
                for (int j = 0; j < 4; j++) {
                    mma_bf16(acc[i][j], ah[i], bh[j]);
                    mma_bf16(acc[i][j], ah[i], bl[j]);
                    mma_bf16(acc[i][j], al[i], bh[j]);
                }
        }
        __syncthreads();
    }

    const int rb = row0 + warp_m * 64 + (lane >> 2);
    const int cb = col0 + warp_n * 32 + (lane & 3) * 2;
#pragma unroll
    for (int i = 0; i < 4; i++)
#pragma unroll
        for (int j = 0; j < 4; j++) {
            float* p0 = C + (size_t)(rb + i * 16) * N + cb + j * 8;
            float* p1 = C + (size_t)(rb + i * 16 + 8) * N + cb + j * 8;
            *(float2*)p0 = make_float2(acc[i][j][0], acc[i][j][1]);
            *(float2*)p1 = make_float2(acc[i][j][2], acc[i][j][3]);
        }
}

// ---------------------------------------------------------------------------
// fp32 -> split bf16 (hi/lo)
// ---------------------------------------------------------------------------
__global__ void split_kernel(const float* __restrict__ x,
                             __nv_bfloat16* __restrict__ hi,
                             __nv_bfloat16* __restrict__ lo, int n4)
{
    int i = blockIdx.x * blockDim.x + threadIdx.x;
    if (i >= n4) return;
    float4 v = ((const float4*)x)[i];
    float vv[4] = {v.x, v.y, v.z, v.w};
    __nv_bfloat16 hv[4], lv[4];
#pragma unroll
    for (int j = 0; j < 4; j++) {
        hv[j] = __float2bfloat16_rn(vv[j]);
        lv[j] = __float2bfloat16_rn(vv[j] - __bfloat162float(hv[j]));
    }
    *(uint2*)&hi[(size_t)i * 4] = *(uint2*)hv;
    *(uint2*)&lo[(size_t)i * 4] = *(uint2*)lv;
}

// ---------------------------------------------------------------------------
// fp32 [R][Cn] -> transposed split bf16 [Cn][R] (hi/lo). 32x32 tiles.
// ---------------------------------------------------------------------------
__global__ void tsplit_kernel(const float* __restrict__ x,
                              __nv_bfloat16* __restrict__ hi,
                              __nv_bfloat16* __restrict__ lo, int R, int Cn)
{
    __shared__ float t[32][33];
    int bc = blockIdx.x * 32, br = blockIdx.y * 32;
    int tx = threadIdx.x, ty = threadIdx.y;
#pragma unroll
    for (int j = 0; j < 32; j += 8)
        t[ty + j][tx] = x[(size_t)(br + ty + j) * Cn + bc + tx];
    __syncthreads();
#pragma unroll
    for (int j = 0; j < 32; j += 8) {
        int orow = bc + ty + j;
        int ocol = br + tx;
        float v = t[tx][ty + j];
        __nv_bfloat16 h = __float2bfloat16_rn(v);
        hi[(size_t)orow * R + ocol] = h;
        lo[(size_t)orow * R + ocol] = __float2bfloat16_rn(v - __bfloat162float(h));
    }
}

// ---------------------------------------------------------------------------
// Fused RoPE + split: qkv fp32 -> q/k/v bf16 hi/lo buffers
// ---------------------------------------------------------------------------
__global__ void rope_split_kernel(
    const float* __restrict__ qkv, const int* __restrict__ positions,
    __nv_bfloat16* __restrict__ qhi, __nv_bfloat16* __restrict__ qlo,
    __nv_bfloat16* __restrict__ khi, __nv_bfloat16* __restrict__ klo,
    __nv_bfloat16* __restrict__ vhi, __nv_bfloat16* __restrict__ vlo)
{
    const int total = MROWS * 11 * 128;
    int idx = blockIdx.x * blockDim.x + threadIdx.x;
    if (idx >= total) return;
    int j = idx & 127;
    int t = idx >> 7;
    int unit = t % 11;
    int row = t / 11;
    int s = row & (SS - 1);
    int b = row >> 11;

    if (unit < 9) {
        float pos = (float)positions[s];
        const float LOG_THETA = 9.210340371976184f;
        float e = (float)j * (1.0f / 128.0f);
        float invf = expf(-LOG_THETA * e);
        float ang = pos * invf;
        float sn, cs;
        sincosf(ang, &sn, &cs);

        int inoff = row * QKVW + (unit < 8 ? unit * 256 : 2048);
        float x1 = qkv[inoff + j];
        float x2 = qkv[inoff + 128 + j];
        float y1 = x1 * cs - x2 * sn;
        float y2 = x2 * cs + x1 * sn;

        size_t ooff;
        __nv_bfloat16 *ph, *pl;
        if (unit < 8) {
            ooff = ((size_t)(b * NHH + unit) * SS + s) * DD;
            ph = qhi; pl = qlo;
        } else {
            ooff = (size_t)row * DD;
            ph = khi; pl = klo;
        }
        __nv_bfloat16 h1 = __float2bfloat16_rn(y1);
        __nv_bfloat16 h2 = __float2bfloat16_rn(y2);
        ph[ooff + j] = h1;
        ph[ooff + 128 + j] = h2;
        pl[ooff + j] = __float2bfloat16_rn(y1 - __bfloat162float(h1));
        pl[ooff + 128 + j] = __float2bfloat16_rn(y2 - __bfloat162float(h2));
    } else {
        int jj = (unit - 9) * 128 + j;
        float v = qkv[row * QKVW + 2304 + jj];
        __nv_bfloat16 h = __float2bfloat16_rn(v);
        vhi[(size_t)row * DD + jj] = h;
        vlo[(size_t)row * DD + jj] = __float2bfloat16_rn(v - __bfloat162float(h));
    }
}

// ---------------------------------------------------------------------------
// HMMA flash attention v2: Br=128, Bc=32, 256 threads (8 warps).
// Warp w owns Q rows w*16..w*16+15 -> softmax stays warp-local.
// 2 warps per SMSP for latency hiding.
// ---------------------------------------------------------------------------
#define KSTR 528                       // Q/K/V smem row stride bytes (256 bf16 + pad)
#define PSTR 80                        // P smem row stride bytes (32 bf16 + pad)
#define FQHI 0
#define FQLO (FQHI + 128 * KSTR)       // 67584
#define FKHI (FQLO + 128 * KSTR)       // 135168
#define FKLO (FKHI + 32 * KSTR)        // +16896
#define FVHI (FKLO + 32 * KSTR)
#define FVLO (FVHI + 32 * KSTR)
#define FPHI (FVLO + 32 * KSTR)        // 202752
#define FPLO (FPHI + 128 * PSTR)       // +10240
#define FLASH_SMEM (FPLO + 128 * PSTR) // 223232

__global__ __launch_bounds__(256) void flash_hmma_kernel(
    const __nv_bfloat16* __restrict__ Qhi, const __nv_bfloat16* __restrict__ Qlo,
    const __nv_bfloat16* __restrict__ Khi, const __nv_bfloat16* __restrict__ Klo,
    const __nv_bfloat16* __restrict__ Vhi, const __nv_bfloat16* __restrict__ Vlo,
    __nv_bfloat16* __restrict__ Ohi, __nv_bfloat16* __restrict__ Olo)
{
    extern __shared__ char fsm[];
    const uint32_t base = smem_u32(fsm);
    const int qt = (gridDim.x - 1) - blockIdx.x;   // big tiles first
    const int h = blockIdx.y, b = blockIdx.z;
    const int tid = threadIdx.x, lane = tid & 31, w = tid >> 5;
    const int q0 = qt * 128;
    const int nj = (q0 + 128) >> 5;                // # of 32-wide KV tiles

    const __nv_bfloat16* qhp = Qhi + ((size_t)(b * NHH + h) * SS + q0) * DD;
    const __nv_bfloat16* qlp = Qlo + ((size_t)(b * NHH + h) * SS + q0) * DD;
    const __nv_bfloat16* khp = Khi + (size_t)b * SS * DD;
    const __nv_bfloat16* klp = Klo + (size_t)b * SS * DD;
    const __nv_bfloat16* vhp = Vhi + (size_t)b * SS * DD;
    const __nv_bfloat16* vlp = Vlo + (size_t)b * SS * DD;

    // Q load: 128 rows hi+lo, one group
    {
#pragma unroll
        for (int i = 0; i < 16; i++) {
            int g = tid + (i << 8);
            int r = g >> 5, cq = g & 31;
            cp16(base + FQHI + r * KSTR + (cq << 4),
                 qhp + (size_t)r * DD + (cq << 3));
        }
#pragma unroll
        for (int i = 0; i < 16; i++) {
            int g = tid + (i << 8);
            int r = g >> 5, cq = g & 31;
            cp16(base + FQLO + r * KSTR + (cq << 4),
                 qlp + (size_t)r * DD + (cq << 3));
        }
        asm volatile("cp.async.commit_group;" ::: "memory");
    }

    // K/V tile loader: 32 rows hi+lo, one group
    auto ldkv = [&](uint32_t offhi, uint32_t offlo, const __nv_bfloat16* ph,
                    const __nv_bfloat16* pl, int c0) {
#pragma unroll
        for (int i = 0; i < 4; i++) {
            int g = tid + (i << 8);
            int r = g >> 5, cq = g & 31;
            cp16(base + offhi + r * KSTR + (cq << 4),
                 ph + (size_t)(c0 + r) * DD + (cq << 3));
        }
#pragma unroll
        for (int i = 0; i < 4; i++) {
            int g = tid + (i << 8);
            int r = g >> 5, cq = g & 31;
            cp16(base + offlo + r * KSTR + (cq << 4),
                 pl + (size_t)(c0 + r) * DD + (cq << 3));
        }
        asm volatile("cp.async.commit_group;" ::: "memory");
    };

    ldkv(FKHI, FKLO, khp, klp, 0);     // K0
    ldkv(FVHI, FVLO, vhp, vlp, 0);     // V0

    float acc[32][4];
#pragma unroll
    for (int t = 0; t < 32; t++)
#pragma unroll
        for (int e = 0; e < 4; e++) acc[t][e] = 0.f;
    float m0 = -1e30f, m1 = -1e30f, l0 = 0.f, l1 = 0.f;

    const uint32_t aQbase = base + FQHI + (w * 16 + (lane & 15)) * KSTR + ((lane >> 4) << 4);
    const int quad = lane >> 3, wi = lane & 7;
    const uint32_t bKbase = base + FKHI + ((quad >> 1) * 8 + wi) * KSTR + ((quad & 1) << 4);
    const uint32_t aPbase = base + FPHI + (w * 16 + (lane & 15)) * PSTR + ((lane >> 4) << 4);
    const uint32_t bVbase = base + FVHI + ((lane & 7) + ((lane >> 3) & 1) * 8) * KSTR
                          + (lane >> 4) * 16;
    const uint32_t pstore = base + FPHI + (w * 16 + (lane >> 2)) * PSTR + (lane & 3) * 4;
    const float scale = 0.0625f;

    for (int jt = 0; jt < nj; jt++) {
        const int c0 = jt * 32;
        // K(jt) ready (V(jt) may stay pending)
        asm volatile("cp.async.wait_group 1;" ::: "memory");
        __syncthreads();

        // ---------------- S = Q K^T : S[16x32] per warp ----------------
        float sacc[4][4];
#pragma unroll
        for (int t = 0; t < 4; t++)
#pragma unroll
            for (int e = 0; e < 4; e++) sacc[t][e] = 0.f;

#pragma unroll
        for (int ks = 0; ks < 16; ks++) {
            uint32_t ah[4], al[4];
            ldsm_x4(ah, aQbase + ks * 32);
            ldsm_x4(al, aQbase + (FQLO - FQHI) + ks * 32);
#pragma unroll
            for (int np = 0; np < 2; np++) {
                uint32_t bh4[4], bl4[4];
                uint32_t ka = bKbase + np * 16 * KSTR + ks * 32;
                ldsm_x4(bh4, ka);
                ldsm_x4(bl4, ka + (FKLO - FKHI));
                mma_bf16(sacc[2 * np],     ah, bh4);
                mma_bf16(sacc[2 * np],     ah, bl4);
                mma_bf16(sacc[2 * np],     al, bh4);
                mma_bf16(sacc[2 * np + 1], ah, bh4 + 2);
                mma_bf16(sacc[2 * np + 1], ah, bl4 + 2);
                mma_bf16(sacc[2 * np + 1], al, bh4 + 2);
            }
        }
        __syncthreads();                           // done reading K smem
        if (jt + 1 < nj) ldkv(FKHI, FKLO, khp, klp, c0 + 32);   // prefetch K(jt+1)

        // ---------------- softmax (warp-local rows) ----------------
        const int colb = c0 + (lane & 3) * 2;
        const int row0g = q0 + w * 16 + (lane >> 2);
        const int row1g = row0g + 8;
        if (c0 + 31 > q0) {        // diagonal band: apply causal mask
#pragma unroll
            for (int t = 0; t < 4; t++) {
                int cg = colb + t * 8;
#pragma unroll
                for (int e = 0; e < 4; e++) {
                    float v = sacc[t][e] * scale;
                    int c = cg + (e & 1);
                    int rg = (e < 2) ? row0g : row1g;
                    if (c > rg) v = -1e30f;
                    sacc[t][e] = v;
                }
            }
        } else {
#pragma unroll
            for (int t = 0; t < 4; t++)
#pragma unroll
                for (int e = 0; e < 4; e++) sacc[t][e] *= scale;
        }
        float mx0 = -1e30f, mx1 = -1e30f;
#pragma unroll
        for (int t = 0; t < 4; t++) {
            mx0 = fmaxf(mx0, fmaxf(sacc[t][0], sacc[t][1]));
            mx1 = fmaxf(mx1, fmaxf(sacc[t][2], sacc[t][3]));
        }
        mx0 = fmaxf(mx0, __shfl_xor_sync(0xffffffffu, mx0, 1));
        mx0 = fmaxf(mx0, __shfl_xor_sync(0xffffffffu, mx0, 2));
        mx1 = fmaxf(mx1, __shfl_xor_sync(0xffffffffu, mx1, 1));
        mx1 = fmaxf(mx1, __shfl_xor_sync(0xffffffffu, mx1, 2));

        float mn0 = fmaxf(m0, mx0), mn1 = fmaxf(m1, mx1);
        float a0 = __expf(m0 - mn0), a1 = __expf(m1 - mn1);
        m0 = mn0; m1 = mn1;
        float s0 = 0.f, s1 = 0.f;
#pragma unroll
        for (int t = 0; t < 4; t++) {
            float p0 = __expf(sacc[t][0] - mn0);
            float p1 = __expf(sacc[t][1] - mn0);
            float p2 = __expf(sacc[t][2] - mn1);
            float p3 = __expf(sacc[t][3] - mn1);
            s0 += p0 + p1; s1 += p2 + p3;
            uint32_t h01 = pk_bf2(p0, p1);
            uint32_t h23 = pk_bf2(p2, p3);
            __nv_bfloat162* hp = (__nv_bfloat162*)&h01;
            __nv_bfloat162* hq = (__nv_bfloat162*)&h23;
            uint32_t lo01 = pk_bf2(p0 - __bfloat162float(hp->x), p1 - __bfloat162float(hp->y));
            uint32_t lo23 = pk_bf2(p2 - __bfloat162float(hq->x), p3 - __bfloat162float(hq->y));
            asm volatile("st.shared.b32 [%0], %1;" :: "r"(pstore + t * 16), "r"(h01) : "memory");
            asm volatile("st.shared.b32 [%0], %1;" :: "r"(pstore + 8 * PSTR + t * 16), "r"(h23) : "memory");
            asm volatile("st.shared.b32 [%0], %1;" :: "r"(pstore + (FPLO - FPHI) + t * 16), "r"(lo01) : "memory");
            asm volatile("st.shared.b32 [%0], %1;" :: "r"(pstore + (FPLO - FPHI) + 8 * PSTR + t * 16), "r"(lo23) : "memory");
        }
        s0 += __shfl_xor_sync(0xffffffffu, s0, 1);
        s0 += __shfl_xor_sync(0xffffffffu, s0, 2);
        s1 += __shfl_xor_sync(0xffffffffu, s1, 1);
        s1 += __shfl_xor_sync(0xffffffffu, s1, 2);
        l0 = l0 * a0 + s0;
        l1 = l1 * a1 + s1;
#pragma unroll
        for (int t = 0; t < 32; t++) {
            acc[t][0] *= a0; acc[t][1] *= a0;
            acc[t][2] *= a1; acc[t][3] *= a1;
        }

        // V(jt) ready; prefetched K(jt+1) may stay pending
        if (jt + 1 < nj) { asm volatile("cp.async.wait_group 1;" ::: "memory"); }
        else             { asm volatile("cp.async.wait_group 0;" ::: "memory"); }
        __syncthreads();     // V visible + P stores ordered

        // ---------------- O += P V : P[16x32] @ V[32x256] ----------------
#pragma unroll
        for (int ks = 0; ks < 2; ks++) {
            uint32_t ph4[4], pl4[4];
            ldsm_x4(ph4, aPbase + ks * 32);
            ldsm_x4(pl4, aPbase + (FPLO - FPHI) + ks * 32);
#pragma unroll
            for (int np = 0; np < 16; np++) {
                uint32_t vh4[4], vl4[4];
                uint32_t va = bVbase + ks * 16 * KSTR + np * 32;
                ldsm_x4_t(vh4, va);
                ldsm_x4_t(vl4, va + (FVLO - FVHI));
                mma_bf16(acc[2 * np],     ph4, vh4);
                mma_bf16(acc[2 * np],     pl4, vh4);
                mma_bf16(acc[2 * np],     ph4, vl4);
                mma_bf16(acc[2 * np + 1], ph4, vh4 + 2);
                mma_bf16(acc[2 * np + 1], pl4, vh4 + 2);
                mma_bf16(acc[2 * np + 1], ph4, vl4 + 2);
            }
        }
        __syncthreads();                           // done reading V smem
        if (jt + 1 < nj) ldkv(FVHI, FVLO, vhp, vlp, c0 + 32);   // prefetch V(jt+1)
    }

    // ---------------- epilogue ----------------
    float inv0 = 1.0f / l0, inv1 = 1.0f / l1;
    size_t ob0 = ((size_t)(b * SS) + q0 + w * 16 + (lane >> 2)) * HH + h * DD + (lane & 3) * 2;
    size_t ob1 = ob0 + 8 * (size_t)HH;
#pragma unroll
    for (int t = 0; t < 32; t++) {
        float o0 = acc[t][0] * inv0, o1 = acc[t][1] * inv0;
        float o2 = acc[t][2] * inv1, o3 = acc[t][3] * inv1;
        uint32_t h01 = pk_bf2(o0, o1);
        uint32_t h23 = pk_bf2(o2, o3);
        __nv_bfloat162* hp = (__nv_bfloat162*)&h01;
        __nv_bfloat162* hq = (__nv_bfloat162*)&h23;
        uint32_t lo01 = pk_bf2(o0 - __bfloat162float(hp->x), o1 - __bfloat162float(hp->y));
        uint32_t lo23 = pk_bf2(o2 - __bfloat162float(hq->x), o3 - __bfloat162float(hq->y));
        *(uint32_t*)&Ohi[ob0 + t * 8] = h01;
        *(uint32_t*)&Ohi[ob1 + t * 8] = h23;
        *(uint32_t*)&Olo[ob0 + t * 8] = lo01;
        *(uint32_t*)&Olo[ob1 + t * 8] = lo23;
    }
}

// ---------------------------------------------------------------------------
extern "C" void kernel_launch(void* const* d_in, const int* in_sizes, int n_in,
                              void* d_out, int out_size)
{
    const float* hidden    = (const float*)d_in[0];
    const int*   positions = (const int*)d_in[1];
    const float* w_qkv     = (const float*)d_in[2];
    const float* w_o       = (const float*)d_in[3];
    float* out = (float*)d_out;

    float* qkv_ptr;
    __nv_bfloat16 *hid_hi, *hid_lo, *wqkv_hi, *wqkv_lo, *wo_hi, *wo_lo, *atn_hi, *atn_lo;
    __nv_bfloat16 *q_hi, *q_lo, *k_hi, *k_lo, *v_hi, *v_lo;
    cudaGetSymbolAddress((void**)&qkv_ptr, g_qkv);
    cudaGetSymbolAddress((void**)&hid_hi, g_hid_hi);
    cudaGetSymbolAddress((void**)&hid_lo, g_hid_lo);
    cudaGetSymbolAddress((void**)&wqkv_hi, g_wqkv_hi);
    cudaGetSymbolAddress((void**)&wqkv_lo, g_wqkv_lo);
    cudaGetSymbolAddress((void**)&wo_hi, g_wo_hi);
    cudaGetSymbolAddress((void**)&wo_lo, g_wo_lo);
    cudaGetSymbolAddress((void**)&atn_hi, g_atn_hi);
    cudaGetSymbolAddress((void**)&atn_lo, g_atn_lo);
    cudaGetSymbolAddress((void**)&q_hi, g_q_hi);
    cudaGetSymbolAddress((void**)&q_lo, g_q_lo);
    cudaGetSymbolAddress((void**)&k_hi, g_k_hi);
    cudaGetSymbolAddress((void**)&k_lo, g_k_lo);
    cudaGetSymbolAddress((void**)&v_hi, g_v_hi);
    cudaGetSymbolAddress((void**)&v_lo, g_v_lo);

    cudaFuncSetAttribute(hmma_gemm_kernel,
                         cudaFuncAttributeMaxDynamicSharedMemorySize, GEMM_SMEM);
    cudaFuncSetAttribute(flash_hmma_kernel,
                         cudaFuncAttributeMaxDynamicSharedMemorySize, FLASH_SMEM);

    // 1) split hidden -> bf16 hi/lo
    {
        int n4 = MROWS * HH / 4;
        split_kernel<<<(n4 + 255) / 256, 256>>>(hidden, hid_hi, hid_lo, n4);
    }
    // 2) transpose+split w_qkv
    tsplit_kernel<<<dim3(QKVW / 32, HH / 32), dim3(32, 8)>>>(w_qkv, wqkv_hi, wqkv_lo, HH, QKVW);

    // 3) QKV projection (HMMA split-bf16)
    hmma_gemm_kernel<<<dim3(QKVW / 128, MROWS / 128), 256, GEMM_SMEM>>>(
        hid_hi, hid_lo, wqkv_hi, wqkv_lo, qkv_ptr, MROWS, QKVW, HH);

    // 4) fused RoPE + split -> q/k/v hi/lo
    {
        int total = MROWS * 11 * 128;
        rope_split_kernel<<<(total + 255) / 256, 256>>>(
            qkv_ptr, positions, q_hi, q_lo, k_hi, k_lo, v_hi, v_lo);
    }

    // 5) HMMA flash attention v2 (Br=128, Bc=32, 8 warps)
    {
        dim3 grid2(SS / 128, NHH, BB);
        flash_hmma_kernel<<<grid2, 256, FLASH_SMEM>>>(
            q_hi, q_lo, k_hi, k_lo, v_hi, v_lo, atn_hi, atn_lo);
    }

    // 6) transpose+split w_o
    tsplit_kernel<<<dim3(HH / 32, HH / 32), dim3(32, 8)>>>(w_o, wo_hi, wo_lo, HH, HH);

    // 7) Output projection (HMMA split-bf16)
    hmma_gemm_kernel<<<dim3(HH / 128, MROWS / 128), 256, GEMM_SMEM>>>(
        atn_hi, atn_lo, wo_hi, wo_lo, out, MROWS, HH, HH);
}

// round 6
// speedup vs baseline: 1.0091x; 1.0091x over previous
#include <cuda_runtime.h>
#include <cuda_bf16.h>
#include <math.h>
#include <stdint.h>

#define BB 4
#define SS 2048
#define HH 2048
#define NHH 8
#define DD 256
#define QKVW 2560            // (8 + 2*1) * 256
#define MROWS (BB * SS)      // 8192

// ---------------------------------------------------------------------------
// Scratch (allocation-free rule: device globals)
// ---------------------------------------------------------------------------
__device__ float g_qkv[MROWS * QKVW];                         // ~84 MB fp32
__device__ __align__(16) __nv_bfloat16 g_hid_hi[MROWS * HH];
__device__ __align__(16) __nv_bfloat16 g_hid_lo[MROWS * HH];
__device__ __align__(16) __nv_bfloat16 g_wqkv_hi[QKVW * HH];  // transposed [N][K]
__device__ __align__(16) __nv_bfloat16 g_wqkv_lo[QKVW * HH];
__device__ __align__(16) __nv_bfloat16 g_wo_hi[HH * HH];      // transposed [N][K]
__device__ __align__(16) __nv_bfloat16 g_wo_lo[HH * HH];
__device__ __align__(16) __nv_bfloat16 g_atn_hi[MROWS * HH];
__device__ __align__(16) __nv_bfloat16 g_atn_lo[MROWS * HH];
__device__ __align__(16) __nv_bfloat16 g_q_hi[(size_t)BB * NHH * SS * DD];
__device__ __align__(16) __nv_bfloat16 g_q_lo[(size_t)BB * NHH * SS * DD];
__device__ __align__(16) __nv_bfloat16 g_k_hi[(size_t)BB * SS * DD];
__device__ __align__(16) __nv_bfloat16 g_k_lo[(size_t)BB * SS * DD];
__device__ __align__(16) __nv_bfloat16 g_v_hi[(size_t)BB * SS * DD];
__device__ __align__(16) __nv_bfloat16 g_v_lo[(size_t)BB * SS * DD];

// ---------------------------------------------------------------------------
// helpers
// ---------------------------------------------------------------------------
__device__ __forceinline__ uint32_t smem_u32(const void* p) {
    uint32_t a;
    asm("{ .reg .u64 t; cvta.to.shared.u64 t, %1; cvt.u32.u64 %0, t; }"
        : "=r"(a) : "l"(p));
    return a;
}

__device__ __forceinline__ void ldsm_x4(uint32_t (&r)[4], uint32_t addr) {
    asm volatile("ldmatrix.sync.aligned.m8n8.x4.shared.b16 {%0,%1,%2,%3}, [%4];"
                 : "=r"(r[0]), "=r"(r[1]), "=r"(r[2]), "=r"(r[3]) : "r"(addr));
}

__device__ __forceinline__ void ldsm_x4_t(uint32_t (&r)[4], uint32_t addr) {
    asm volatile("ldmatrix.sync.aligned.m8n8.x4.trans.shared.b16 {%0,%1,%2,%3}, [%4];"
                 : "=r"(r[0]), "=r"(r[1]), "=r"(r[2]), "=r"(r[3]) : "r"(addr));
}

__device__ __forceinline__ void mma_bf16(float (&d)[4], const uint32_t (&a)[4],
                                         const uint32_t* b) {
    asm volatile(
        "mma.sync.aligned.m16n8k16.row.col.f32.bf16.bf16.f32 "
        "{%0,%1,%2,%3}, {%4,%5,%6,%7}, {%8,%9}, {%0,%1,%2,%3};"
        : "+f"(d[0]), "+f"(d[1]), "+f"(d[2]), "+f"(d[3])
        : "r"(a[0]), "r"(a[1]), "r"(a[2]), "r"(a[3]), "r"(b[0]), "r"(b[1]));
}

__device__ __forceinline__ void cp16(uint32_t dst, const void* src) {
    asm volatile("cp.async.cg.shared.global [%0], [%1], 16;"
                 :: "r"(dst), "l"(src) : "memory");
}

__device__ __forceinline__ uint32_t pk_bf2(float a, float b) {
    __nv_bfloat162 t = __floats2bfloat162_rn(a, b);
    return *reinterpret_cast<uint32_t*>(&t);
}

// ---------------------------------------------------------------------------
// HMMA split-bf16 GEMM, 4-stage cp.async pipeline (prefetch distance 3),
// ONE syncthreads per K-chunk. 256 threads, block 128x128x32.
// ---------------------------------------------------------------------------
#define ROWB 80
#define TILEB (128 * ROWB)
#define STAGEB (4 * TILEB)        // 40960 per stage
#define GEMM_SMEM (4 * STAGEB)    // 163840

__global__ __launch_bounds__(256) void hmma_gemm_kernel(
    const __nv_bfloat16* __restrict__ Ahi, const __nv_bfloat16* __restrict__ Alo,
    const __nv_bfloat16* __restrict__ Bhi, const __nv_bfloat16* __restrict__ Blo,
    float* __restrict__ C, int M, int N, int K)
{
    extern __shared__ char gsm[];
    const uint32_t base = smem_u32(gsm);

    const int tid = threadIdx.x;
    const int lane = tid & 31;
    const int wid = tid >> 5;
    const int warp_m = wid & 1;
    const int warp_n = wid >> 1;
    const int row0 = blockIdx.y * 128, col0 = blockIdx.x * 128;

    float acc[4][4][4];
#pragma unroll
    for (int i = 0; i < 4; i++)
#pragma unroll
        for (int j = 0; j < 4; j++)
#pragma unroll
            for (int e = 0; e < 4; e++) acc[i][j][e] = 0.f;

    const int nch = K >> 5;      // 64 for K=2048 (always >= 3 here)

    auto load_stage = [&](int st, int k0) {
        const uint32_t sb = base + st * STAGEB;
#pragma unroll
        for (int i2 = 0; i2 < 8; i2++) {
            int g = tid + (i2 << 8);
            int t = g >> 9;
            int rem = g & 511;
            int r = rem >> 2, kq = rem & 3;
            const __nv_bfloat16* bp = (t == 0) ? Ahi : (t == 1) ? Alo
                                    : (t == 2) ? Bhi : Blo;
            int gr = ((t < 2) ? row0 : col0) + r;
            const __nv_bfloat16* src = bp + (size_t)gr * K + k0 + (kq << 3);
            uint32_t dst = sb + t * TILEB + r * ROWB + (kq << 4);
            cp16(dst, src);
        }
        asm volatile("cp.async.commit_group;" ::: "memory");
    };

    load_stage(0, 0);
    load_stage(1, 32);
    load_stage(2, 64);

    for (int c = 0; c < nch; c++) {
        const int rem = nch - 1 - c;      // groups issued after stage c
        if (rem >= 2)      { asm volatile("cp.async.wait_group 2;" ::: "memory"); }
        else if (rem == 1) { asm volatile("cp.async.wait_group 1;" ::: "memory"); }
        else               { asm volatile("cp.async.wait_group 0;" ::: "memory"); }
        __syncthreads();   // stage c visible to all; all warps past chunk c-1 reads

        if (c + 3 < nch) load_stage((c + 3) & 3, (c + 3) << 5);

        const uint32_t sb = base + (c & 3) * STAGEB;
        const uint32_t aH = sb, bH = sb + 2 * TILEB;

#pragma unroll
        for (int ks = 0; ks < 2; ks++) {
            uint32_t ah[4][4], al[4][4], bh[4][2], bl[4][2];
            const int arow = warp_m * 64 + (lane & 15);
            const uint32_t akoff = (ks << 5) + ((lane >> 4) << 4);
#pragma unroll
            for (int i = 0; i < 4; i++) {
                uint32_t ad = aH + (uint32_t)(arow + i * 16) * ROWB + akoff;
                ldsm_x4(ah[i], ad);
                ldsm_x4(al[i], ad + TILEB);
            }
            const int quad = lane >> 3, wi = lane & 7;
#pragma unroll
            for (int t = 0; t < 2; t++) {
                int ntile = 2 * t + (quad >> 1);
                int brow = warp_n * 32 + ntile * 8 + wi;
                uint32_t bd = bH + (uint32_t)brow * ROWB + (ks << 5) + ((quad & 1) << 4);
                uint32_t r4[4];
                ldsm_x4(r4, bd);
                bh[2 * t][0] = r4[0]; bh[2 * t][1] = r4[1];
                bh[2 * t + 1][0] = r4[2]; bh[2 * t + 1][1] = r4[3];
                ldsm_x4(r4, bd + TILEB);
                bl[2 * t][0] = r4[0]; bl[2 * t][1] = r4[1];
                bl[2 * t + 1][0] = r4[2]; bl[2 * t + 1][1] = r4[3];
            }
#pragma unroll
            for (int i = 0; i < 4; i++)
#pragma unroll
                for (int j = 0; j < 4; j++) {
                    mma_bf16(acc[i][j], ah[i], bh[j]);
                    mma_bf16(acc[i][j], ah[i], bl[j]);
                    mma_bf16(acc[i][j], al[i], bh[j]);
                }
        }
    }

    const int rb = row0 + warp_m * 64 + (lane >> 2);
    const int cb = col0 + warp_n * 32 + (lane & 3) * 2;
#pragma unroll
    for (int i = 0; i < 4; i++)
#pragma unroll
        for (int j = 0; j < 4; j++) {
            float* p0 = C + (size_t)(rb + i * 16) * N + cb + j * 8;
            float* p1 = C + (size_t)(rb + i * 16 + 8) * N + cb + j * 8;
            *(float2*)p0 = make_float2(acc[i][j][0], acc[i][j][1]);
            *(float2*)p1 = make_float2(acc[i][j][2], acc[i][j][3]);
        }
}

// ---------------------------------------------------------------------------
// fp32 -> split bf16 (hi/lo)
// ---------------------------------------------------------------------------
__global__ void split_kernel(const float* __restrict__ x,
                             __nv_bfloat16* __restrict__ hi,
                             __nv_bfloat16* __restrict__ lo, int n4)
{
    int i = blockIdx.x * blockDim.x + threadIdx.x;
    if (i >= n4) return;
    float4 v = ((const float4*)x)[i];
    float vv[4] = {v.x, v.y, v.z, v.w};
    __nv_bfloat16 hv[4], lv[4];
#pragma unroll
    for (int j = 0; j < 4; j++) {
        hv[j] = __float2bfloat16_rn(vv[j]);
        lv[j] = __float2bfloat16_rn(vv[j] - __bfloat162float(hv[j]));
    }
    *(uint2*)&hi[(size_t)i * 4] = *(uint2*)hv;
    *(uint2*)&lo[(size_t)i * 4] = *(uint2*)lv;
}

// ---------------------------------------------------------------------------
// fp32 [R][Cn] -> transposed split bf16 [Cn][R] (hi/lo). 32x32 tiles.
// ---------------------------------------------------------------------------
__global__ void tsplit_kernel(const float* __restrict__ x,
                              __nv_bfloat16* __restrict__ hi,
                              __nv_bfloat16* __restrict__ lo, int R, int Cn)
{
    __shared__ float t[32][33];
    int bc = blockIdx.x * 32, br = blockIdx.y * 32;
    int tx = threadIdx.x, ty = threadIdx.y;
#pragma unroll
    for (int j = 0; j < 32; j += 8)
        t[ty + j][tx] = x[(size_t)(br + ty + j) * Cn + bc + tx];
    __syncthreads();
#pragma unroll
    for (int j = 0; j < 32; j += 8) {
        int orow = bc + ty + j;
        int ocol = br + tx;
        float v = t[tx][ty + j];
        __nv_bfloat16 h = __float2bfloat16_rn(v);
        hi[(size_t)orow * R + ocol] = h;
        lo[(size_t)orow * R + ocol] = __float2bfloat16_rn(v - __bfloat162float(h));
    }
}

// ---------------------------------------------------------------------------
// Fused RoPE + split. Q is PRE-SCALED by 1/16 (softmax scale folded in).
// ---------------------------------------------------------------------------
__global__ void rope_split_kernel(
    const float* __restrict__ qkv, const int* __restrict__ positions,
    __nv_bfloat16* __restrict__ qhi, __nv_bfloat16* __restrict__ qlo,
    __nv_bfloat16* __restrict__ khi, __nv_bfloat16* __restrict__ klo,
    __nv_bfloat16* __restrict__ vhi, __nv_bfloat16* __restrict__ vlo)
{
    const int total = MROWS * 11 * 128;
    int idx = blockIdx.x * blockDim.x + threadIdx.x;
    if (idx >= total) return;
    int j = idx & 127;
    int t = idx >> 7;
    int unit = t % 11;
    int row = t / 11;
    int s = row & (SS - 1);
    int b = row >> 11;

    if (unit < 9) {
        float pos = (float)positions[s];
        const float LOG_THETA = 9.210340371976184f;
        float e = (float)j * (1.0f / 128.0f);
        float invf = expf(-LOG_THETA * e);
        float ang = pos * invf;
        float sn, cs;
        sincosf(ang, &sn, &cs);

        int inoff = row * QKVW + (unit < 8 ? unit * 256 : 2048);
        float x1 = qkv[inoff + j];
        float x2 = qkv[inoff + 128 + j];
        float y1 = x1 * cs - x2 * sn;
        float y2 = x2 * cs + x1 * sn;

        size_t ooff;
        __nv_bfloat16 *ph, *pl;
        if (unit < 8) {
            y1 *= 0.0625f;     // fold softmax scale into Q
            y2 *= 0.0625f;
            ooff = ((size_t)(b * NHH + unit) * SS + s) * DD;
            ph = qhi; pl = qlo;
        } else {
            ooff = (size_t)row * DD;
            ph = khi; pl = klo;
        }
        __nv_bfloat16 h1 = __float2bfloat16_rn(y1);
        __nv_bfloat16 h2 = __float2bfloat16_rn(y2);
        ph[ooff + j] = h1;
        ph[ooff + 128 + j] = h2;
        pl[ooff + j] = __float2bfloat16_rn(y1 - __bfloat162float(h1));
        pl[ooff + 128 + j] = __float2bfloat16_rn(y2 - __bfloat162float(h2));
    } else {
        int jj = (unit - 9) * 128 + j;
        float v = qkv[row * QKVW + 2304 + jj];
        __nv_bfloat16 h = __float2bfloat16_rn(v);
        vhi[(size_t)row * DD + jj] = h;
        vlo[(size_t)row * DD + jj] = __float2bfloat16_rn(v - __bfloat162float(h));
    }
}

// ---------------------------------------------------------------------------
// HMMA flash attention v2: Br=128, Bc=32, 256 threads (8 warps).
// Q pre-scaled. Conditional acc-rescale (skip when running max unchanged).
// ---------------------------------------------------------------------------
#define KSTR 528
#define PSTR 80
#define FQHI 0
#define FQLO (FQHI + 128 * KSTR)
#define FKHI (FQLO + 128 * KSTR)
#define FKLO (FKHI + 32 * KSTR)
#define FVHI (FKLO + 32 * KSTR)
#define FVLO (FVHI + 32 * KSTR)
#define FPHI (FVLO + 32 * KSTR)
#define FPLO (FPHI + 128 * PSTR)
#define FLASH_SMEM (FPLO + 128 * PSTR)

__global__ __launch_bounds__(256) void flash_hmma_kernel(
    const __nv_bfloat16* __restrict__ Qhi, const __nv_bfloat16* __restrict__ Qlo,
    const __nv_bfloat16* __restrict__ Khi, const __nv_bfloat16* __restrict__ Klo,
    const __nv_bfloat16* __restrict__ Vhi, const __nv_bfloat16* __restrict__ Vlo,
    __nv_bfloat16* __restrict__ Ohi, __nv_bfloat16* __restrict__ Olo)
{
    extern __shared__ char fsm[];
    const uint32_t base = smem_u32(fsm);
    const int qt = (gridDim.x - 1) - blockIdx.x;   // big tiles first
    const int h = blockIdx.y, b = blockIdx.z;
    const int tid = threadIdx.x, lane = tid & 31, w = tid >> 5;
    const int q0 = qt * 128;
    const int nj = (q0 + 128) >> 5;

    const __nv_bfloat16* qhp = Qhi + ((size_t)(b * NHH + h) * SS + q0) * DD;
    const __nv_bfloat16* qlp = Qlo + ((size_t)(b * NHH + h) * SS + q0) * DD;
    const __nv_bfloat16* khp = Khi + (size_t)b * SS * DD;
    const __nv_bfloat16* klp = Klo + (size_t)b * SS * DD;
    const __nv_bfloat16* vhp = Vhi + (size_t)b * SS * DD;
    const __nv_bfloat16* vlp = Vlo + (size_t)b * SS * DD;

    {
#pragma unroll
        for (int i = 0; i < 16; i++) {
            int g = tid + (i << 8);
            int r = g >> 5, cq = g & 31;
            cp16(base + FQHI + r * KSTR + (cq << 4),
                 qhp + (size_t)r * DD + (cq << 3));
        }
#pragma unroll
        for (int i = 0; i < 16; i++) {
            int g = tid + (i << 8);
            int r = g >> 5, cq = g & 31;
            cp16(base + FQLO + r * KSTR + (cq << 4),
                 qlp + (size_t)r * DD + (cq << 3));
        }
        asm volatile("cp.async.commit_group;" ::: "memory");
    }

    auto ldkv = [&](uint32_t offhi, uint32_t offlo, const __nv_bfloat16* ph,
                    const __nv_bfloat16* pl, int c0) {
#pragma unroll
        for (int i = 0; i < 4; i++) {
            int g = tid + (i << 8);
            int r = g >> 5, cq = g & 31;
            cp16(base + offhi + r * KSTR + (cq << 4),
                 ph + (size_t)(c0 + r) * DD + (cq << 3));
        }
#pragma unroll
        for (int i = 0; i < 4; i++) {
            int g = tid + (i << 8);
            int r = g >> 5, cq = g & 31;
            cp16(base + offlo + r * KSTR + (cq << 4),
                 pl + (size_t)(c0 + r) * DD + (cq << 3));
        }
        asm volatile("cp.async.commit_group;" ::: "memory");
    };

    ldkv(FKHI, FKLO, khp, klp, 0);
    ldkv(FVHI, FVLO, vhp, vlp, 0);

    float acc[32][4];
#pragma unroll
    for (int t = 0; t < 32; t++)
#pragma unroll
        for (int e = 0; e < 4; e++) acc[t][e] = 0.f;
    float m0 = -1e30f, m1 = -1e30f, l0 = 0.f, l1 = 0.f;

    const uint32_t aQbase = base + FQHI + (w * 16 + (lane & 15)) * KSTR + ((lane >> 4) << 4);
    const int quad = lane >> 3, wi = lane & 7;
    const uint32_t bKbase = base + FKHI + ((quad >> 1) * 8 + wi) * KSTR + ((quad & 1) << 4);
    const uint32_t aPbase = base + FPHI + (w * 16 + (lane & 15)) * PSTR + ((lane >> 4) << 4);
    const uint32_t bVbase = base + FVHI + ((lane & 7) + ((lane >> 3) & 1) * 8) * KSTR
                          + (lane >> 4) * 16;
    const uint32_t pstore = base + FPHI + (w * 16 + (lane >> 2)) * PSTR + (lane & 3) * 4;

    for (int jt = 0; jt < nj; jt++) {
        const int c0 = jt * 32;
        asm volatile("cp.async.wait_group 1;" ::: "memory");
        __syncthreads();

        // ---------------- S = Q K^T ----------------
        float sacc[4][4];
#pragma unroll
        for (int t = 0; t < 4; t++)
#pragma unroll
            for (int e = 0; e < 4; e++) sacc[t][e] = 0.f;

#pragma unroll
        for (int ks = 0; ks < 16; ks++) {
            uint32_t ah[4], al[4];
            ldsm_x4(ah, aQbase + ks * 32);
            ldsm_x4(al, aQbase + (FQLO - FQHI) + ks * 32);
#pragma unroll
            for (int np = 0; np < 2; np++) {
                uint32_t bh4[4], bl4[4];
                uint32_t ka = bKbase + np * 16 * KSTR + ks * 32;
                ldsm_x4(bh4, ka);
                ldsm_x4(bl4, ka + (FKLO - FKHI));
                mma_bf16(sacc[2 * np],     ah, bh4);
                mma_bf16(sacc[2 * np],     ah, bl4);
                mma_bf16(sacc[2 * np],     al, bh4);
                mma_bf16(sacc[2 * np + 1], ah, bh4 + 2);
                mma_bf16(sacc[2 * np + 1], ah, bl4 + 2);
                mma_bf16(sacc[2 * np + 1], al, bh4 + 2);
            }
        }
        __syncthreads();
        if (jt + 1 < nj) ldkv(FKHI, FKLO, khp, klp, c0 + 32);

        // ---------------- softmax (scale pre-folded into Q) ----------------
        const int colb = c0 + (lane & 3) * 2;
        const int row0g = q0 + w * 16 + (lane >> 2);
        const int row1g = row0g + 8;
        if (c0 + 31 > q0) {
#pragma unroll
            for (int t = 0; t < 4; t++) {
                int cg = colb + t * 8;
#pragma unroll
                for (int e = 0; e < 4; e++) {
                    int c = cg + (e & 1);
                    int rg = (e < 2) ? row0g : row1g;
                    if (c > rg) sacc[t][e] = -1e30f;
                }
            }
        }
        float mx0 = -1e30f, mx1 = -1e30f;
#pragma unroll
        for (int t = 0; t < 4; t++) {
            mx0 = fmaxf(mx0, fmaxf(sacc[t][0], sacc[t][1]));
            mx1 = fmaxf(mx1, fmaxf(sacc[t][2], sacc[t][3]));
        }
        mx0 = fmaxf(mx0, __shfl_xor_sync(0xffffffffu, mx0, 1));
        mx0 = fmaxf(mx0, __shfl_xor_sync(0xffffffffu, mx0, 2));
        mx1 = fmaxf(mx1, __shfl_xor_sync(0xffffffffu, mx1, 1));
        mx1 = fmaxf(mx1, __shfl_xor_sync(0xffffffffu, mx1, 2));

        float mn0 = fmaxf(m0, mx0), mn1 = fmaxf(m1, mx1);
        float a0 = __expf(m0 - mn0), a1 = __expf(m1 - mn1);
        m0 = mn0; m1 = mn1;
        float s0 = 0.f, s1 = 0.f;
#pragma unroll
        for (int t = 0; t < 4; t++) {
            float p0 = __expf(sacc[t][0] - mn0);
            float p1 = __expf(sacc[t][1] - mn0);
            float p2 = __expf(sacc[t][2] - mn1);
            float p3 = __expf(sacc[t][3] - mn1);
            s0 += p0 + p1; s1 += p2 + p3;
            uint32_t h01 = pk_bf2(p0, p1);
            uint32_t h23 = pk_bf2(p2, p3);
            __nv_bfloat162* hp = (__nv_bfloat162*)&h01;
            __nv_bfloat162* hq = (__nv_bfloat162*)&h23;
            uint32_t lo01 = pk_bf2(p0 - __bfloat162float(hp->x), p1 - __bfloat162float(hp->y));
            uint32_t lo23 = pk_bf2(p2 - __bfloat162float(hq->x), p3 - __bfloat162float(hq->y));
            asm volatile("st.shared.b32 [%0], %1;" :: "r"(pstore + t * 16), "r"(h01) : "memory");
            asm volatile("st.shared.b32 [%0], %1;" :: "r"(pstore + 8 * PSTR + t * 16), "r"(h23) : "memory");
            asm volatile("st.shared.b32 [%0], %1;" :: "r"(pstore + (FPLO - FPHI) + t * 16), "r"(lo01) : "memory");
            asm volatile("st.shared.b32 [%0], %1;" :: "r"(pstore + (FPLO - FPHI) + 8 * PSTR + t * 16), "r"(lo23) : "memory");
        }
        s0 += __shfl_xor_sync(0xffffffffu, s0, 1);
        s0 += __shfl_xor_sync(0xffffffffu, s0, 2);
        s1 += __shfl_xor_sync(0xffffffffu, s1, 1);
        s1 += __shfl_xor_sync(0xffffffffu, s1, 2);
        l0 = l0 * a0 + s0;
        l1 = l1 * a1 + s1;
        // conditional rescale: skip the 128 FFMAs when no row max moved
        bool noresc = __all_sync(0xffffffffu, (a0 == 1.0f) && (a1 == 1.0f));
        if (!noresc) {
#pragma unroll
            for (int t = 0; t < 32; t++) {
                acc[t][0] *= a0; acc[t][1] *= a0;
                acc[t][2] *= a1; acc[t][3] *= a1;
            }
        }

        if (jt + 1 < nj) { asm volatile("cp.async.wait_group 1;" ::: "memory"); }
        else             { asm volatile("cp.async.wait_group 0;" ::: "memory"); }
        __syncthreads();

        // ---------------- O += P V ----------------
#pragma unroll
        for (int ks = 0; ks < 2; ks++) {
            uint32_t ph4[4], pl4[4];
            ldsm_x4(ph4, aPbase + ks * 32);
            ldsm_x4(pl4, aPbase + (FPLO - FPHI) + ks * 32);
#pragma unroll
            for (int np = 0; np < 16; np++) {
                uint32_t vh4[4], vl4[4];
                uint32_t va = bVbase + ks * 16 * KSTR + np * 32;
                ldsm_x4_t(vh4, va);
                ldsm_x4_t(vl4, va + (FVLO - FVHI));
                mma_bf16(acc[2 * np],     ph4, vh4);
                mma_bf16(acc[2 * np],     pl4, vh4);
                mma_bf16(acc[2 * np],     ph4, vl4);
                mma_bf16(acc[2 * np + 1], ph4, vh4 + 2);
                mma_bf16(acc[2 * np + 1], pl4, vh4 + 2);
                mma_bf16(acc[2 * np + 1], ph4, vl4 + 2);
            }
        }
        __syncthreads();
        if (jt + 1 < nj) ldkv(FVHI, FVLO, vhp, vlp, c0 + 32);
    }

    // ---------------- epilogue ----------------
    float inv0 = 1.0f / l0, inv1 = 1.0f / l1;
    size_t ob0 = ((size_t)(b * SS) + q0 + w * 16 + (lane >> 2)) * HH + h * DD + (lane & 3) * 2;
    size_t ob1 = ob0 + 8 * (size_t)HH;
#pragma unroll
    for (int t = 0; t < 32; t++) {
        float o0 = acc[t][0] * inv0, o1 = acc[t][1] * inv0;
        float o2 = acc[t][2] * inv1, o3 = acc[t][3] * inv1;
        uint32_t h01 = pk_bf2(o0, o1);
        uint32_t h23 = pk_bf2(o2, o3);
        __nv_bfloat162* hp = (__nv_bfloat162*)&h01;
        __nv_bfloat162* hq = (__nv_bfloat162*)&h23;
        uint32_t lo01 = pk_bf2(o0 - __bfloat162float(hp->x), o1 - __bfloat162float(hp->y));
        uint32_t lo23 = pk_bf2(o2 - __bfloat162float(hq->x), o3 - __bfloat162float(hq->y));
        *(uint32_t*)&Ohi[ob0 + t * 8] = h01;
        *(uint32_t*)&Ohi[ob1 + t * 8] = h23;
        *(uint32_t*)&Olo[ob0 + t * 8] = lo01;
        *(uint32_t*)&Olo[ob1 + t * 8] = lo23;
    }
}

// ---------------------------------------------------------------------------
extern "C" void kernel_launch(void* const* d_in, const int* in_sizes, int n_in,
                              void* d_out, int out_size)
{
    const float* hidden    = (const float*)d_in[0];
    const int*   positions = (const int*)d_in[1];
    const float* w_qkv     = (const float*)d_in[2];
    const float* w_o       = (const float*)d_in[3];
    float* out = (float*)d_out;

    float* qkv_ptr;
    __nv_bfloat16 *hid_hi, *hid_lo, *wqkv_hi, *wqkv_lo, *wo_hi, *wo_lo, *atn_hi, *atn_lo;
    __nv_bfloat16 *q_hi, *q_lo, *k_hi, *k_lo, *v_hi, *v_lo;
    cudaGetSymbolAddress((void**)&qkv_ptr, g_qkv);
    cudaGetSymbolAddress((void**)&hid_hi, g_hid_hi);
    cudaGetSymbolAddress((void**)&hid_lo, g_hid_lo);
    cudaGetSymbolAddress((void**)&wqkv_hi, g_wqkv_hi);
    cudaGetSymbolAddress((void**)&wqkv_lo, g_wqkv_lo);
    cudaGetSymbolAddress((void**)&wo_hi, g_wo_hi);
    cudaGetSymbolAddress((void**)&wo_lo, g_wo_lo);
    cudaGetSymbolAddress((void**)&atn_hi, g_atn_hi);
    cudaGetSymbolAddress((void**)&atn_lo, g_atn_lo);
    cudaGetSymbolAddress((void**)&q_hi, g_q_hi);
    cudaGetSymbolAddress((void**)&q_lo, g_q_lo);
    cudaGetSymbolAddress((void**)&k_hi, g_k_hi);
    cudaGetSymbolAddress((void**)&k_lo, g_k_lo);
    cudaGetSymbolAddress((void**)&v_hi, g_v_hi);
    cudaGetSymbolAddress((void**)&v_lo, g_v_lo);

    cudaFuncSetAttribute(hmma_gemm_kernel,
                         cudaFuncAttributeMaxDynamicSharedMemorySize, GEMM_SMEM);
    cudaFuncSetAttribute(flash_hmma_kernel,
                         cudaFuncAttributeMaxDynamicSharedMemorySize, FLASH_SMEM);

    // 1) split hidden -> bf16 hi/lo
    {
        int n4 = MROWS * HH / 4;
        split_kernel<<<(n4 + 255) / 256, 256>>>(hidden, hid_hi, hid_lo, n4);
    }
    // 2) transpose+split w_qkv
    tsplit_kernel<<<dim3(QKVW / 32, HH / 32), dim3(32, 8)>>>(w_qkv, wqkv_hi, wqkv_lo, HH, QKVW);

    // 3) QKV projection (HMMA split-bf16, 4-stage)
    hmma_gemm_kernel<<<dim3(QKVW / 128, MROWS / 128), 256, GEMM_SMEM>>>(
        hid_hi, hid_lo, wqkv_hi, wqkv_lo, qkv_ptr, MROWS, QKVW, HH);

    // 4) fused RoPE + split (Q pre-scaled)
    {
        int total = MROWS * 11 * 128;
        rope_split_kernel<<<(total + 255) / 256, 256>>>(
            qkv_ptr, positions, q_hi, q_lo, k_hi, k_lo, v_hi, v_lo);
    }

    // 5) HMMA flash attention v2
    {
        dim3 grid2(SS / 128, NHH, BB);
        flash_hmma_kernel<<<grid2, 256, FLASH_SMEM>>>(
            q_hi, q_lo, k_hi, k_lo, v_hi, v_lo, atn_hi, atn_lo);
    }

    // 6) transpose+split w_o
    tsplit_kernel<<<dim3(HH / 32, HH / 32), dim3(32, 8)>>>(w_o, wo_hi, wo_lo, HH, HH);

    // 7) Output projection (HMMA split-bf16, 4-stage)
    hmma_gemm_kernel<<<dim3(HH / 128, MROWS / 128), 256, GEMM_SMEM>>>(
        atn_hi, atn_lo, wo_hi, wo_lo, out, MROWS, HH, HH);
}